// round 12
// baseline (speedup 1.0000x reference)
#include <cuda_runtime.h>
#include <cuda_bf16.h>
#include <cstdint>
#include <math.h>

// ---------------------------------------------------------------------------
// Problem constants
// ---------------------------------------------------------------------------
#define NROWS 8192
#define DIM   256
constexpr float INV_TEMP = 1.0f / 0.07f;
constexpr float ALPHA = 1.44269504088896341f / 0.07f;  // log2(e)/T, folded into X

// Banding: each CTA owns a 256-column B panel; A streams in 64-row strips.
#define BAND   256
#define SROWS  64
#define SPB    128                       // strips per band (8192/64)
#define TSTRIPS 4096                     // 32 bands * 128 strips
#define GRIDSZ 152                       // one CTA per SM

// SMEM: B panel 128KB resident + A double buffer 2x32KB = 192KB
#define ROWB   512                       // bytes per smem row (256 bf16)
#define SM_B   0
#define SM_A(p) (BAND * ROWB + (p) * (SROWS * ROWB))
#define SMEM_TOTAL (BAND * ROWB + 2 * SROWS * ROWB)   // 196608

// ---------------------------------------------------------------------------
// Scratch (device globals; no allocations allowed)
// ---------------------------------------------------------------------------
__device__ float g_rowsum[NROWS];
__device__ float g_diag[NROWS];
__device__ unsigned int g_ctr;
__device__ float* g_outp;
__device__ __nv_bfloat16 g_xb[NROWS * DIM];   // x * ALPHA, bf16
__device__ __nv_bfloat16 g_yb[NROWS * DIM];   // y, bf16

// ---------------------------------------------------------------------------
// Helpers
// ---------------------------------------------------------------------------
__device__ __forceinline__ uint32_t smem_to_u32(const void* p) {
    uint32_t a;
    asm("{ .reg .u64 t; cvta.to.shared.u64 t, %1; cvt.u32.u64 %0, t; }"
        : "=r"(a) : "l"(p));
    return a;
}
__device__ __forceinline__ void cp16(uint32_t saddr, const void* gaddr) {
    asm volatile("cp.async.cg.shared.global [%0], [%1], 16;"
                 :: "r"(saddr), "l"(gaddr) : "memory");
}
#define CP_COMMIT()  asm volatile("cp.async.commit_group;" ::: "memory")
#define CP_WAIT0()   asm volatile("cp.async.wait_group 0;" ::: "memory")

#define LDSM4(r0, r1, r2, r3, addr)                                          \
    asm volatile("ldmatrix.sync.aligned.m8n8.x4.shared.b16 {%0,%1,%2,%3}, [%4];" \
                 : "=r"(r0), "=r"(r1), "=r"(r2), "=r"(r3) : "r"(addr))

#define MMA16816(d, a, b0, b1)                                               \
    asm volatile("mma.sync.aligned.m16n8k16.row.col.f32.bf16.bf16.f32 "      \
                 "{%0,%1,%2,%3}, {%4,%5,%6,%7}, {%8,%9}, {%0,%1,%2,%3};"     \
                 : "+f"(d[0]), "+f"(d[1]), "+f"(d[2]), "+f"(d[3])            \
                 : "r"(a[0]), "r"(a[1]), "r"(a[2]), "r"(a[3]),               \
                   "r"(b0), "r"(b1))

__device__ __forceinline__ float ex2f(float x) {
    float v;
    asm("ex2.approx.ftz.f32 %0, %1;" : "=f"(v) : "f"(x));
    return v;
}
__device__ __forceinline__ float lg2f(float x) {
    float v;
    asm("lg2.approx.ftz.f32 %0, %1;" : "=f"(v) : "f"(x));
    return v;
}

// Swizzled smem address: row stride 512B, XOR low-3 16B-chunk bits with row&7
#define SWA(base, r, c) ((base) + (r) * ROWB + ((((c) ^ ((r) & 7))) << 4))

// ---------------------------------------------------------------------------
// Kernel: fused prep — convert X*ALPHA and Y to bf16, diag dots, zero rowsum,
// zero completion counter, stash the output pointer.
// ---------------------------------------------------------------------------
__global__ __launch_bounds__(256) void prep_kernel(const float* __restrict__ X,
                                                   const float* __restrict__ Y,
                                                   float* out) {
    const int warp = threadIdx.x >> 5, lane = threadIdx.x & 31;
    const int r = blockIdx.x * 8 + warp;
    const float4* X4 = reinterpret_cast<const float4*>(X) + (size_t)r * (DIM / 4);
    const float4* Y4 = reinterpret_cast<const float4*>(Y) + (size_t)r * (DIM / 4);
    float s = 0.0f;
    #pragma unroll
    for (int i = 0; i < 2; i++) {
        int idx = lane + 32 * i;
        float4 a = X4[idx];
        float4 b = Y4[idx];
        s += a.x * b.x + a.y * b.y + a.z * b.z + a.w * b.w;
        __nv_bfloat162 ax = __floats2bfloat162_rn(a.x * ALPHA, a.y * ALPHA);
        __nv_bfloat162 ay = __floats2bfloat162_rn(a.z * ALPHA, a.w * ALPHA);
        __nv_bfloat162 bx = __floats2bfloat162_rn(b.x, b.y);
        __nv_bfloat162 by = __floats2bfloat162_rn(b.z, b.w);
        uint2 ua, ub;
        ua.x = *reinterpret_cast<uint32_t*>(&ax);
        ua.y = *reinterpret_cast<uint32_t*>(&ay);
        ub.x = *reinterpret_cast<uint32_t*>(&bx);
        ub.y = *reinterpret_cast<uint32_t*>(&by);
        *reinterpret_cast<uint2*>(g_xb + (size_t)r * DIM + idx * 4) = ua;
        *reinterpret_cast<uint2*>(g_yb + (size_t)r * DIM + idx * 4) = ub;
    }
    #pragma unroll
    for (int o = 16; o > 0; o >>= 1) s += __shfl_xor_sync(0xFFFFFFFFu, s, o);
    if (lane == 0) {
        g_diag[r] = s;
        g_rowsum[r] = 0.0f;
    }
    if (blockIdx.x == 0 && threadIdx.x == 0) {
        g_ctr = 0u;
        g_outp = out;
    }
}

// ---------------------------------------------------------------------------
// GEMM: B-resident band kernel with exp-epilogue interleaved into the k-loop
// (round-6 champion, unchanged) + a register-light last-CTA loss tail.
// ---------------------------------------------------------------------------
__device__ __forceinline__ void load_B_panel(uint32_t Bb, int band, int tid) {
    const __nv_bfloat16* Bg = g_yb + (size_t)band * BAND * DIM;
    #pragma unroll
    for (int it = 0; it < 32; it++) {
        int idx = tid + it * 256;
        int r = idx >> 5, c = idx & 31;
        cp16(SWA(Bb, r, c), Bg + (size_t)r * DIM + c * 8);
    }
}
__device__ __forceinline__ void load_A_strip(uint32_t Ab, int srow, int tid) {
    const __nv_bfloat16* Ag = g_xb + (size_t)srow * SROWS * DIM;
    #pragma unroll
    for (int it = 0; it < 8; it++) {
        int idx = tid + it * 256;
        int r = idx >> 5, c = idx & 31;
        cp16(SWA(Ab, r, c), Ag + (size_t)r * DIM + c * 8);
    }
}

// Compute strip into aN while doing the exp-epilogue of aO (rows row_old..+63).
__device__ __forceinline__ void strip_compute(
    uint32_t Ab, uint32_t Bb, int n_base,
    int a_row_off, int a_c_off, int b_row_off, int b_c_off,
    float (&aN)[4][4][4], float (&aO)[4][4][4],
    int row_old, int lid)
{
    #pragma unroll
    for (int i = 0; i < 4; i++)
        #pragma unroll
        for (int j = 0; j < 4; j++)
            #pragma unroll
            for (int r = 0; r < 4; r++) aN[i][j][r] = 0.0f;

    float lo[4] = {0.f, 0.f, 0.f, 0.f}, hi[4] = {0.f, 0.f, 0.f, 0.f};

    #pragma unroll
    for (int kk = 0; kk < 16; kk++) {
        uint32_t a[4][4];
        #pragma unroll
        for (int mi = 0; mi < 4; mi++) {
            int row = mi * 16 + a_row_off;
            int c = kk * 2 + a_c_off;
            LDSM4(a[mi][0], a[mi][1], a[mi][2], a[mi][3], SWA(Ab, row, c));
        }
        uint32_t b[2][4];
        #pragma unroll
        for (int p = 0; p < 2; p++) {
            int nrow = n_base + p * 16 + b_row_off;
            int c = kk * 2 + b_c_off;
            LDSM4(b[p][0], b[p][1], b[p][2], b[p][3], SWA(Bb, nrow, c));
        }
        // Interleave 4 elements of the previous strip's exp-epilogue.
        #pragma unroll
        for (int j = 0; j < 4; j++) {
            int e = kk * 4 + j;
            int mi = e >> 4, ni = (e >> 2) & 3, r = e & 3;
            float v = ex2f(aO[mi][ni][r]);
            if (r < 2) lo[mi] += v; else hi[mi] += v;
        }
        #pragma unroll
        for (int mi = 0; mi < 4; mi++)
            #pragma unroll
            for (int ni = 0; ni < 4; ni++)
                MMA16816(aN[mi][ni], a[mi],
                         b[ni >> 1][(ni & 1) << 1],
                         b[ni >> 1][((ni & 1) << 1) + 1]);
    }

    // Finish previous strip: quad-shuffle row reduce + atomics.
    const int g = lid >> 2;
    #pragma unroll
    for (int mi = 0; mi < 4; mi++) {
        float l = lo[mi], h = hi[mi];
        l += __shfl_xor_sync(0xFFFFFFFFu, l, 1);
        l += __shfl_xor_sync(0xFFFFFFFFu, l, 2);
        h += __shfl_xor_sync(0xFFFFFFFFu, h, 1);
        h += __shfl_xor_sync(0xFFFFFFFFu, h, 2);
        if ((lid & 3) == 0) {
            atomicAdd(&g_rowsum[row_old + mi * 16 + g], l);
            atomicAdd(&g_rowsum[row_old + mi * 16 + g + 8], h);
        }
    }
}

// Epilogue-only flush for the final strip.
__device__ __forceinline__ void flush_acc(float (&aO)[4][4][4], int row_old, int lid) {
    const int g = lid >> 2;
    #pragma unroll
    for (int mi = 0; mi < 4; mi++) {
        float l = 0.f, h = 0.f;
        #pragma unroll
        for (int ni = 0; ni < 4; ni++) {
            l += ex2f(aO[mi][ni][0]) + ex2f(aO[mi][ni][1]);
            h += ex2f(aO[mi][ni][2]) + ex2f(aO[mi][ni][3]);
        }
        l += __shfl_xor_sync(0xFFFFFFFFu, l, 1);
        l += __shfl_xor_sync(0xFFFFFFFFu, l, 2);
        h += __shfl_xor_sync(0xFFFFFFFFu, h, 1);
        h += __shfl_xor_sync(0xFFFFFFFFu, h, 2);
        if ((lid & 3) == 0) {
            atomicAdd(&g_rowsum[row_old + mi * 16 + g], l);
            atomicAdd(&g_rowsum[row_old + mi * 16 + g + 8], h);
        }
    }
}

__global__ __launch_bounds__(256, 1) void simsum_hmma_kernel() {
    extern __shared__ char smem[];
    const uint32_t sb = smem_to_u32(smem);
    const int tid = threadIdx.x;
    const int wid = tid >> 5, lid = tid & 31;
    const int n_base = wid * 32;               // warp grid 1 (M) x 8 (N)

    const int sub = lid >> 3, l7 = lid & 7;
    const int a_row_off = ((sub & 1) << 3) + l7;
    const int a_c_off   = sub >> 1;
    const int b_row_off = ((sub >> 1) << 3) + l7;
    const int b_c_off   = sub & 1;

    const int start = (int)(((long)blockIdx.x * TSTRIPS) / GRIDSZ);
    const int end   = (int)(((long)(blockIdx.x + 1) * TSTRIPS) / GRIDSZ);

    // Ping-pong accumulators; init so the first (fake) epilogue adds 0.
    float accA[4][4][4], accB[4][4][4];
    #pragma unroll
    for (int i = 0; i < 4; i++)
        #pragma unroll
        for (int j = 0; j < 4; j++)
            #pragma unroll
            for (int r = 0; r < 4; r++) { accA[i][j][r] = -1e30f; accB[i][j][r] = -1e30f; }

    int row_old = 0;
    int pcur = 0;
    for (int w = start; w < end; w++) {
        const int band = w >> 7, srow = w & (SPB - 1);
        if (srow == 0 || w == start) {
            CP_WAIT0();
            __syncthreads();                   // all warps done with old B panel
            load_B_panel(sb + SM_B, band, tid);
            load_A_strip(sb + SM_A(0), srow, tid);
            CP_COMMIT();
            CP_WAIT0();
            __syncthreads();
            pcur = 0;
        } else {
            CP_WAIT0();                        // prefetched A strip landed
            __syncthreads();
        }
        const bool pf = (w + 1 < end) && (((w + 1) & (SPB - 1)) != 0);
        if (pf) {
            load_A_strip(sb + SM_A(pcur ^ 1), srow + 1, tid);
            CP_COMMIT();
        }

        if ((w - start) & 1)
            strip_compute(sb + SM_A(pcur), sb + SM_B, n_base,
                          a_row_off, a_c_off, b_row_off, b_c_off,
                          accB, accA, row_old, lid);
        else
            strip_compute(sb + SM_A(pcur), sb + SM_B, n_base,
                          a_row_off, a_c_off, b_row_off, b_c_off,
                          accA, accB, row_old, lid);

        row_old = srow * SROWS;
        if (pf) pcur ^= 1;
    }

    if ((end - start) & 1) flush_acc(accA, row_old, lid);
    else                   flush_acc(accB, row_old, lid);

    // ---- Fused loss tail (register-light; all state loaded AFTER the loop).
    __threadfence();                 // make this thread's REDs globally visible
    __syncthreads();                 // whole CTA has fenced
    unsigned int* ctr_slot = reinterpret_cast<unsigned int*>(smem + 2048);
    if (tid == 0) *ctr_slot = atomicAdd(&g_ctr, 1u);
    __syncthreads();
    if (*ctr_slot != GRIDSZ - 1) return;
    __threadfence();                 // acquire: order reads after counter win

    float* outp = g_outp;            // loaded post-fence; no live range over loop
    float* sh = reinterpret_cast<float*>(smem);
    float part = 0.0f;
    #pragma unroll 1
    for (int i = tid; i < NROWS; i += 256) {
        float d = g_diag[i] * INV_TEMP;
        float lneg = __ldcg(&g_rowsum[i]) - ex2f(d * 1.44269504f);
        part += lg2f(lneg) * 0.69314718056f - d;
    }
    sh[tid] = part;
    __syncthreads();
    #pragma unroll 1
    for (int o = 128; o > 0; o >>= 1) {
        if (tid < o) sh[tid] += sh[tid + o];
        __syncthreads();
    }
    if (tid == 0) outp[0] = sh[0] * (1.0f / NROWS);
}

// ---------------------------------------------------------------------------
// Entry point
// ---------------------------------------------------------------------------
extern "C" void kernel_launch(void* const* d_in, const int* in_sizes, int n_in,
                              void* d_out, int out_size) {
    const float* X = (const float*)d_in[0];
    const float* Y = (const float*)d_in[1];
    float* out = (float*)d_out;

    static bool attr_set = false;
    if (!attr_set) {
        cudaFuncSetAttribute(simsum_hmma_kernel,
                             cudaFuncAttributeMaxDynamicSharedMemorySize, SMEM_TOTAL);
        attr_set = true;
    }

    prep_kernel<<<NROWS / 8, 256>>>(X, Y, out);
    simsum_hmma_kernel<<<GRIDSZ, 256, SMEM_TOTAL>>>();
}

// round 13
// speedup vs baseline: 1.2236x; 1.2236x over previous
#include <cuda_runtime.h>
#include <cuda_bf16.h>
#include <cstdint>
#include <math.h>

// ---------------------------------------------------------------------------
// Problem constants
// ---------------------------------------------------------------------------
#define NROWS 8192
#define DIM   256
constexpr float INV_TEMP = 1.0f / 0.07f;
constexpr float ALPHA = 1.44269504088896341f / 0.07f;  // log2(e)/T, folded into X

// Banding: each CTA owns a 256-column B panel; A streams in 64-row strips.
#define BAND   256
#define SROWS  64
#define SPB    128                       // strips per band (8192/64)
#define TSTRIPS 4096                     // 32 bands * 128 strips
#define GRIDSZ 152                       // one CTA per SM

// SMEM: B panel 128KB resident + A double buffer 2x32KB = 192KB
#define ROWB   512                       // bytes per smem row (256 bf16)
#define SM_B   0
#define SM_A(p) (BAND * ROWB + (p) * (SROWS * ROWB))
#define SMEM_TOTAL (BAND * ROWB + 2 * SROWS * ROWB)   // 196608

// ---------------------------------------------------------------------------
// Scratch (device globals; no allocations allowed)
// ---------------------------------------------------------------------------
__device__ float g_rowsum[NROWS];
__device__ float g_diag[NROWS];
__device__ __nv_bfloat16 g_xb[NROWS * DIM];   // x * ALPHA, bf16
__device__ __nv_bfloat16 g_yb[NROWS * DIM];   // y, bf16

// ---------------------------------------------------------------------------
// Helpers
// ---------------------------------------------------------------------------
__device__ __forceinline__ uint32_t smem_to_u32(const void* p) {
    uint32_t a;
    asm("{ .reg .u64 t; cvta.to.shared.u64 t, %1; cvt.u32.u64 %0, t; }"
        : "=r"(a) : "l"(p));
    return a;
}
__device__ __forceinline__ void cp16(uint32_t saddr, const void* gaddr) {
    asm volatile("cp.async.cg.shared.global [%0], [%1], 16;"
                 :: "r"(saddr), "l"(gaddr) : "memory");
}
#define CP_COMMIT()  asm volatile("cp.async.commit_group;" ::: "memory")
#define CP_WAIT0()   asm volatile("cp.async.wait_group 0;" ::: "memory")

#define LDSM4(r0, r1, r2, r3, addr)                                          \
    asm volatile("ldmatrix.sync.aligned.m8n8.x4.shared.b16 {%0,%1,%2,%3}, [%4];" \
                 : "=r"(r0), "=r"(r1), "=r"(r2), "=r"(r3) : "r"(addr))

#define MMA16816(d, a, b0, b1)                                               \
    asm volatile("mma.sync.aligned.m16n8k16.row.col.f32.bf16.bf16.f32 "      \
                 "{%0,%1,%2,%3}, {%4,%5,%6,%7}, {%8,%9}, {%0,%1,%2,%3};"     \
                 : "+f"(d[0]), "+f"(d[1]), "+f"(d[2]), "+f"(d[3])            \
                 : "r"(a[0]), "r"(a[1]), "r"(a[2]), "r"(a[3]),               \
                   "r"(b0), "r"(b1))

__device__ __forceinline__ float ex2f(float x) {
    float v;
    asm("ex2.approx.ftz.f32 %0, %1;" : "=f"(v) : "f"(x));
    return v;
}

// Swizzled smem address: row stride 512B, XOR low-3 16B-chunk bits with row&7
#define SWA(base, r, c) ((base) + (r) * ROWB + ((((c) ^ ((r) & 7))) << 4))

// ---------------------------------------------------------------------------
// Kernel: fused prep — convert X*ALPHA and Y to bf16, diag dots, zero rowsum.
// Each warp handles TWO rows; all 8 16B loads issue before the FMA chains
// (MLP=8/thread) to cover DRAM latency.
// ---------------------------------------------------------------------------
__global__ __launch_bounds__(256) void prep_kernel(const float* __restrict__ X,
                                                   const float* __restrict__ Y,
                                                   float* __restrict__ out) {
    const int warp = threadIdx.x >> 5, lane = threadIdx.x & 31;
    const int r0 = blockIdx.x * 16 + warp * 2;
    const int r1 = r0 + 1;

    const float4* X0 = reinterpret_cast<const float4*>(X) + (size_t)r0 * (DIM / 4);
    const float4* X1 = reinterpret_cast<const float4*>(X) + (size_t)r1 * (DIM / 4);
    const float4* Y0 = reinterpret_cast<const float4*>(Y) + (size_t)r0 * (DIM / 4);
    const float4* Y1 = reinterpret_cast<const float4*>(Y) + (size_t)r1 * (DIM / 4);

    // 8 independent 16B loads per thread
    float4 a0 = X0[2 * lane], a1 = X0[2 * lane + 1];
    float4 a2 = X1[2 * lane], a3 = X1[2 * lane + 1];
    float4 b0 = Y0[2 * lane], b1 = Y0[2 * lane + 1];
    float4 b2 = Y1[2 * lane], b3 = Y1[2 * lane + 1];

    float s0 = a0.x * b0.x + a0.y * b0.y + a0.z * b0.z + a0.w * b0.w
             + a1.x * b1.x + a1.y * b1.y + a1.z * b1.z + a1.w * b1.w;
    float s1 = a2.x * b2.x + a2.y * b2.y + a2.z * b2.z + a2.w * b2.w
             + a3.x * b3.x + a3.y * b3.y + a3.z * b3.z + a3.w * b3.w;

    uint4 ua0, ua1, ub0, ub1;
    {
        __nv_bfloat162 t0 = __floats2bfloat162_rn(a0.x * ALPHA, a0.y * ALPHA);
        __nv_bfloat162 t1 = __floats2bfloat162_rn(a0.z * ALPHA, a0.w * ALPHA);
        __nv_bfloat162 t2 = __floats2bfloat162_rn(a1.x * ALPHA, a1.y * ALPHA);
        __nv_bfloat162 t3 = __floats2bfloat162_rn(a1.z * ALPHA, a1.w * ALPHA);
        ua0.x = *reinterpret_cast<uint32_t*>(&t0);
        ua0.y = *reinterpret_cast<uint32_t*>(&t1);
        ua0.z = *reinterpret_cast<uint32_t*>(&t2);
        ua0.w = *reinterpret_cast<uint32_t*>(&t3);
    }
    {
        __nv_bfloat162 t0 = __floats2bfloat162_rn(a2.x * ALPHA, a2.y * ALPHA);
        __nv_bfloat162 t1 = __floats2bfloat162_rn(a2.z * ALPHA, a2.w * ALPHA);
        __nv_bfloat162 t2 = __floats2bfloat162_rn(a3.x * ALPHA, a3.y * ALPHA);
        __nv_bfloat162 t3 = __floats2bfloat162_rn(a3.z * ALPHA, a3.w * ALPHA);
        ua1.x = *reinterpret_cast<uint32_t*>(&t0);
        ua1.y = *reinterpret_cast<uint32_t*>(&t1);
        ua1.z = *reinterpret_cast<uint32_t*>(&t2);
        ua1.w = *reinterpret_cast<uint32_t*>(&t3);
    }
    {
        __nv_bfloat162 t0 = __floats2bfloat162_rn(b0.x, b0.y);
        __nv_bfloat162 t1 = __floats2bfloat162_rn(b0.z, b0.w);
        __nv_bfloat162 t2 = __floats2bfloat162_rn(b1.x, b1.y);
        __nv_bfloat162 t3 = __floats2bfloat162_rn(b1.z, b1.w);
        ub0.x = *reinterpret_cast<uint32_t*>(&t0);
        ub0.y = *reinterpret_cast<uint32_t*>(&t1);
        ub0.z = *reinterpret_cast<uint32_t*>(&t2);
        ub0.w = *reinterpret_cast<uint32_t*>(&t3);
    }
    {
        __nv_bfloat162 t0 = __floats2bfloat162_rn(b2.x, b2.y);
        __nv_bfloat162 t1 = __floats2bfloat162_rn(b2.z, b2.w);
        __nv_bfloat162 t2 = __floats2bfloat162_rn(b3.x, b3.y);
        __nv_bfloat162 t3 = __floats2bfloat162_rn(b3.z, b3.w);
        ub1.x = *reinterpret_cast<uint32_t*>(&t0);
        ub1.y = *reinterpret_cast<uint32_t*>(&t1);
        ub1.z = *reinterpret_cast<uint32_t*>(&t2);
        ub1.w = *reinterpret_cast<uint32_t*>(&t3);
    }
    *reinterpret_cast<uint4*>(g_xb + (size_t)r0 * DIM + lane * 8) = ua0;
    *reinterpret_cast<uint4*>(g_xb + (size_t)r1 * DIM + lane * 8) = ua1;
    *reinterpret_cast<uint4*>(g_yb + (size_t)r0 * DIM + lane * 8) = ub0;
    *reinterpret_cast<uint4*>(g_yb + (size_t)r1 * DIM + lane * 8) = ub1;

    #pragma unroll
    for (int o = 16; o > 0; o >>= 1) {
        s0 += __shfl_xor_sync(0xFFFFFFFFu, s0, o);
        s1 += __shfl_xor_sync(0xFFFFFFFFu, s1, o);
    }
    if (lane == 0) {
        g_diag[r0] = s0;
        g_diag[r1] = s1;
        g_rowsum[r0] = 0.0f;
        g_rowsum[r1] = 0.0f;
    }
    if (blockIdx.x == 0 && threadIdx.x == 0) out[0] = 0.0f;
}

// ---------------------------------------------------------------------------
// GEMM: B-resident band kernel with exp-epilogue interleaved into the k-loop
// (round-6 champion, byte-for-byte — do NOT add code to this kernel: it sits
// at the 254-register cliff and any addition turns into in-loop spills).
// ---------------------------------------------------------------------------
__device__ __forceinline__ void load_B_panel(uint32_t Bb, int band, int tid) {
    const __nv_bfloat16* Bg = g_yb + (size_t)band * BAND * DIM;
    #pragma unroll
    for (int it = 0; it < 32; it++) {
        int idx = tid + it * 256;
        int r = idx >> 5, c = idx & 31;
        cp16(SWA(Bb, r, c), Bg + (size_t)r * DIM + c * 8);
    }
}
__device__ __forceinline__ void load_A_strip(uint32_t Ab, int srow, int tid) {
    const __nv_bfloat16* Ag = g_xb + (size_t)srow * SROWS * DIM;
    #pragma unroll
    for (int it = 0; it < 8; it++) {
        int idx = tid + it * 256;
        int r = idx >> 5, c = idx & 31;
        cp16(SWA(Ab, r, c), Ag + (size_t)r * DIM + c * 8);
    }
}

// Compute strip into aN while doing the exp-epilogue of aO (rows row_old..+63).
__device__ __forceinline__ void strip_compute(
    uint32_t Ab, uint32_t Bb, int n_base,
    int a_row_off, int a_c_off, int b_row_off, int b_c_off,
    float (&aN)[4][4][4], float (&aO)[4][4][4],
    int row_old, int lid)
{
    #pragma unroll
    for (int i = 0; i < 4; i++)
        #pragma unroll
        for (int j = 0; j < 4; j++)
            #pragma unroll
            for (int r = 0; r < 4; r++) aN[i][j][r] = 0.0f;

    float lo[4] = {0.f, 0.f, 0.f, 0.f}, hi[4] = {0.f, 0.f, 0.f, 0.f};

    #pragma unroll
    for (int kk = 0; kk < 16; kk++) {
        uint32_t a[4][4];
        #pragma unroll
        for (int mi = 0; mi < 4; mi++) {
            int row = mi * 16 + a_row_off;
            int c = kk * 2 + a_c_off;
            LDSM4(a[mi][0], a[mi][1], a[mi][2], a[mi][3], SWA(Ab, row, c));
        }
        uint32_t b[2][4];
        #pragma unroll
        for (int p = 0; p < 2; p++) {
            int nrow = n_base + p * 16 + b_row_off;
            int c = kk * 2 + b_c_off;
            LDSM4(b[p][0], b[p][1], b[p][2], b[p][3], SWA(Bb, nrow, c));
        }
        // Interleave 4 elements of the previous strip's exp-epilogue.
        #pragma unroll
        for (int j = 0; j < 4; j++) {
            int e = kk * 4 + j;
            int mi = e >> 4, ni = (e >> 2) & 3, r = e & 3;
            float v = ex2f(aO[mi][ni][r]);
            if (r < 2) lo[mi] += v; else hi[mi] += v;
        }
        #pragma unroll
        for (int mi = 0; mi < 4; mi++)
            #pragma unroll
            for (int ni = 0; ni < 4; ni++)
                MMA16816(aN[mi][ni], a[mi],
                         b[ni >> 1][(ni & 1) << 1],
                         b[ni >> 1][((ni & 1) << 1) + 1]);
    }

    // Finish previous strip: quad-shuffle row reduce + atomics.
    const int g = lid >> 2;
    #pragma unroll
    for (int mi = 0; mi < 4; mi++) {
        float l = lo[mi], h = hi[mi];
        l += __shfl_xor_sync(0xFFFFFFFFu, l, 1);
        l += __shfl_xor_sync(0xFFFFFFFFu, l, 2);
        h += __shfl_xor_sync(0xFFFFFFFFu, h, 1);
        h += __shfl_xor_sync(0xFFFFFFFFu, h, 2);
        if ((lid & 3) == 0) {
            atomicAdd(&g_rowsum[row_old + mi * 16 + g], l);
            atomicAdd(&g_rowsum[row_old + mi * 16 + g + 8], h);
        }
    }
}

// Epilogue-only flush for the final strip.
__device__ __forceinline__ void flush_acc(float (&aO)[4][4][4], int row_old, int lid) {
    const int g = lid >> 2;
    #pragma unroll
    for (int mi = 0; mi < 4; mi++) {
        float l = 0.f, h = 0.f;
        #pragma unroll
        for (int ni = 0; ni < 4; ni++) {
            l += ex2f(aO[mi][ni][0]) + ex2f(aO[mi][ni][1]);
            h += ex2f(aO[mi][ni][2]) + ex2f(aO[mi][ni][3]);
        }
        l += __shfl_xor_sync(0xFFFFFFFFu, l, 1);
        l += __shfl_xor_sync(0xFFFFFFFFu, l, 2);
        h += __shfl_xor_sync(0xFFFFFFFFu, h, 1);
        h += __shfl_xor_sync(0xFFFFFFFFu, h, 2);
        if ((lid & 3) == 0) {
            atomicAdd(&g_rowsum[row_old + mi * 16 + g], l);
            atomicAdd(&g_rowsum[row_old + mi * 16 + g + 8], h);
        }
    }
}

__global__ __launch_bounds__(256, 1) void simsum_hmma_kernel() {
    extern __shared__ char smem[];
    const uint32_t sb = smem_to_u32(smem);
    const int tid = threadIdx.x;
    const int wid = tid >> 5, lid = tid & 31;
    const int n_base = wid * 32;               // warp grid 1 (M) x 8 (N)

    const int sub = lid >> 3, l7 = lid & 7;
    const int a_row_off = ((sub & 1) << 3) + l7;
    const int a_c_off   = sub >> 1;
    const int b_row_off = ((sub >> 1) << 3) + l7;
    const int b_c_off   = sub & 1;

    const int start = (int)(((long)blockIdx.x * TSTRIPS) / GRIDSZ);
    const int end   = (int)(((long)(blockIdx.x + 1) * TSTRIPS) / GRIDSZ);

    // Ping-pong accumulators; init so the first (fake) epilogue adds 0.
    float accA[4][4][4], accB[4][4][4];
    #pragma unroll
    for (int i = 0; i < 4; i++)
        #pragma unroll
        for (int j = 0; j < 4; j++)
            #pragma unroll
            for (int r = 0; r < 4; r++) { accA[i][j][r] = -1e30f; accB[i][j][r] = -1e30f; }

    int row_old = 0;
    int pcur = 0;
    for (int w = start; w < end; w++) {
        const int band = w >> 7, srow = w & (SPB - 1);
        if (srow == 0 || w == start) {
            CP_WAIT0();
            __syncthreads();                   // all warps done with old B panel
            load_B_panel(sb + SM_B, band, tid);
            load_A_strip(sb + SM_A(0), srow, tid);
            CP_COMMIT();
            CP_WAIT0();
            __syncthreads();
            pcur = 0;
        } else {
            CP_WAIT0();                        // prefetched A strip landed
            __syncthreads();
        }
        const bool pf = (w + 1 < end) && (((w + 1) & (SPB - 1)) != 0);
        if (pf) {
            load_A_strip(sb + SM_A(pcur ^ 1), srow + 1, tid);
            CP_COMMIT();
        }

        if ((w - start) & 1)
            strip_compute(sb + SM_A(pcur), sb + SM_B, n_base,
                          a_row_off, a_c_off, b_row_off, b_c_off,
                          accB, accA, row_old, lid);
        else
            strip_compute(sb + SM_A(pcur), sb + SM_B, n_base,
                          a_row_off, a_c_off, b_row_off, b_c_off,
                          accA, accB, row_old, lid);

        row_old = srow * SROWS;
        if (pf) pcur ^= 1;
    }

    if ((end - start) & 1) flush_acc(accA, row_old, lid);
    else                   flush_acc(accB, row_old, lid);
}

// ---------------------------------------------------------------------------
// Kernel: final loss — one row per thread, 32 blocks, atomic accumulate.
// ---------------------------------------------------------------------------
__global__ __launch_bounds__(256) void loss_kernel(float* __restrict__ out) {
    __shared__ float sh[256];
    int i = blockIdx.x * 256 + threadIdx.x;
    float d = g_diag[i] * INV_TEMP;
    float lneg = g_rowsum[i] - __expf(d);
    sh[threadIdx.x] = logf(lneg) - d;
    __syncthreads();
    #pragma unroll
    for (int o = 128; o > 0; o >>= 1) {
        if (threadIdx.x < o) sh[threadIdx.x] += sh[threadIdx.x + o];
        __syncthreads();
    }
    if (threadIdx.x == 0) atomicAdd(out, sh[0] * (1.0f / NROWS));
}

// ---------------------------------------------------------------------------
// Entry point
// ---------------------------------------------------------------------------
extern "C" void kernel_launch(void* const* d_in, const int* in_sizes, int n_in,
                              void* d_out, int out_size) {
    const float* X = (const float*)d_in[0];
    const float* Y = (const float*)d_in[1];
    float* out = (float*)d_out;

    static bool attr_set = false;
    if (!attr_set) {
        cudaFuncSetAttribute(simsum_hmma_kernel,
                             cudaFuncAttributeMaxDynamicSharedMemorySize, SMEM_TOTAL);
        attr_set = true;
    }

    prep_kernel<<<NROWS / 16, 256>>>(X, Y, out);
    simsum_hmma_kernel<<<GRIDSZ, 256, SMEM_TOTAL>>>();
    loss_kernel<<<NROWS / 256, 256>>>(out);
}

// round 14
// speedup vs baseline: 1.2482x; 1.0202x over previous
#include <cuda_runtime.h>
#include <cuda_bf16.h>
#include <cstdint>
#include <math.h>

// ---------------------------------------------------------------------------
// Problem constants
// ---------------------------------------------------------------------------
#define NROWS 8192
#define DIM   256
constexpr float INV_TEMP = 1.0f / 0.07f;
constexpr float ALPHA = 1.44269504088896341f / 0.07f;  // log2(e)/T, folded into X

// Banding at occupancy 2: each 128-thread CTA owns a 128-column B panel;
// A streams in 32-row strips. Two CTAs per SM cover each other's stalls.
#define THREADS 128
#define GRIDSZ  304                      // 2 persistent CTAs per SM
#define BANDC   128                      // y rows per band
#define SROWS   32                       // x rows per strip
#define SPB     256                      // strips per band (8192/32)
#define NBANDS  64                       // 8192/128
#define TSTRIPS 16384                    // NBANDS * SPB

// SMEM: B panel 64KB resident + A double buffer 2x16KB = 96KB (2 CTAs -> 192KB)
#define ROWB   512                       // bytes per smem row (256 bf16)
#define SM_B   0
#define SM_A(p) (BANDC * ROWB + (p) * (SROWS * ROWB))
#define SMEM_TOTAL (BANDC * ROWB + 2 * SROWS * ROWB)   // 98304

// ---------------------------------------------------------------------------
// Scratch (device globals; no allocations allowed)
// ---------------------------------------------------------------------------
__device__ float g_rowsum[NROWS];
__device__ float g_diag[NROWS];
__device__ __nv_bfloat16 g_xb[NROWS * DIM];   // x * ALPHA, bf16
__device__ __nv_bfloat16 g_yb[NROWS * DIM];   // y, bf16

// ---------------------------------------------------------------------------
// Helpers
// ---------------------------------------------------------------------------
__device__ __forceinline__ uint32_t smem_to_u32(const void* p) {
    uint32_t a;
    asm("{ .reg .u64 t; cvta.to.shared.u64 t, %1; cvt.u32.u64 %0, t; }"
        : "=r"(a) : "l"(p));
    return a;
}
__device__ __forceinline__ void cp16(uint32_t saddr, const void* gaddr) {
    asm volatile("cp.async.cg.shared.global [%0], [%1], 16;"
                 :: "r"(saddr), "l"(gaddr) : "memory");
}
#define CP_COMMIT()  asm volatile("cp.async.commit_group;" ::: "memory")
#define CP_WAIT0()   asm volatile("cp.async.wait_group 0;" ::: "memory")

#define LDSM4(r0, r1, r2, r3, addr)                                          \
    asm volatile("ldmatrix.sync.aligned.m8n8.x4.shared.b16 {%0,%1,%2,%3}, [%4];" \
                 : "=r"(r0), "=r"(r1), "=r"(r2), "=r"(r3) : "r"(addr))

#define MMA16816(d, a, b0, b1)                                               \
    asm volatile("mma.sync.aligned.m16n8k16.row.col.f32.bf16.bf16.f32 "      \
                 "{%0,%1,%2,%3}, {%4,%5,%6,%7}, {%8,%9}, {%0,%1,%2,%3};"     \
                 : "+f"(d[0]), "+f"(d[1]), "+f"(d[2]), "+f"(d[3])            \
                 : "r"(a[0]), "r"(a[1]), "r"(a[2]), "r"(a[3]),               \
                   "r"(b0), "r"(b1))

__device__ __forceinline__ float ex2f(float x) {
    float v;
    asm("ex2.approx.ftz.f32 %0, %1;" : "=f"(v) : "f"(x));
    return v;
}

// Swizzled smem address: row stride 512B, XOR low-3 16B-chunk bits with row&7
#define SWA(base, r, c) ((base) + (r) * ROWB + ((((c) ^ ((r) & 7))) << 4))

// ---------------------------------------------------------------------------
// Kernel: fused prep — convert X*ALPHA and Y to bf16, diag dots, zero rowsum.
// (round-6 proven version)
// ---------------------------------------------------------------------------
__global__ __launch_bounds__(256) void prep_kernel(const float* __restrict__ X,
                                                   const float* __restrict__ Y,
                                                   float* __restrict__ out) {
    const int warp = threadIdx.x >> 5, lane = threadIdx.x & 31;
    const int r = blockIdx.x * 8 + warp;
    const float4* X4 = reinterpret_cast<const float4*>(X) + (size_t)r * (DIM / 4);
    const float4* Y4 = reinterpret_cast<const float4*>(Y) + (size_t)r * (DIM / 4);
    float s = 0.0f;
    #pragma unroll
    for (int i = 0; i < 2; i++) {
        int idx = lane + 32 * i;
        float4 a = X4[idx];
        float4 b = Y4[idx];
        s += a.x * b.x + a.y * b.y + a.z * b.z + a.w * b.w;
        __nv_bfloat162 ax = __floats2bfloat162_rn(a.x * ALPHA, a.y * ALPHA);
        __nv_bfloat162 ay = __floats2bfloat162_rn(a.z * ALPHA, a.w * ALPHA);
        __nv_bfloat162 bx = __floats2bfloat162_rn(b.x, b.y);
        __nv_bfloat162 by = __floats2bfloat162_rn(b.z, b.w);
        uint2 ua, ub;
        ua.x = *reinterpret_cast<uint32_t*>(&ax);
        ua.y = *reinterpret_cast<uint32_t*>(&ay);
        ub.x = *reinterpret_cast<uint32_t*>(&bx);
        ub.y = *reinterpret_cast<uint32_t*>(&by);
        *reinterpret_cast<uint2*>(g_xb + (size_t)r * DIM + idx * 4) = ua;
        *reinterpret_cast<uint2*>(g_yb + (size_t)r * DIM + idx * 4) = ub;
    }
    #pragma unroll
    for (int o = 16; o > 0; o >>= 1) s += __shfl_xor_sync(0xFFFFFFFFu, s, o);
    if (lane == 0) {
        g_diag[r] = s;
        g_rowsum[r] = 0.0f;
    }
    if (blockIdx.x == 0 && threadIdx.x == 0) out[0] = 0.0f;
}

// ---------------------------------------------------------------------------
// GEMM: banded occ=2 kernel. 128 threads (4 warps of 32 N-cols each);
// strip = 32 x-rows; exp-epilogue interleaved into the k-loop as before.
// ---------------------------------------------------------------------------
__device__ __forceinline__ void load_B_panel(uint32_t Bb, int band, int tid) {
    const __nv_bfloat16* Bg = g_yb + (size_t)band * BANDC * DIM;
    #pragma unroll
    for (int it = 0; it < 32; it++) {
        int idx = tid + it * THREADS;      // 0..4095
        int r = idx >> 5, c = idx & 31;
        cp16(SWA(Bb, r, c), Bg + (size_t)r * DIM + c * 8);
    }
}
__device__ __forceinline__ void load_A_strip(uint32_t Ab, int srow, int tid) {
    const __nv_bfloat16* Ag = g_xb + (size_t)srow * SROWS * DIM;
    #pragma unroll
    for (int it = 0; it < 8; it++) {
        int idx = tid + it * THREADS;      // 0..1023
        int r = idx >> 5, c = idx & 31;
        cp16(SWA(Ab, r, c), Ag + (size_t)r * DIM + c * 8);
    }
}

// Compute strip into aN while doing the exp-epilogue of aO (rows row_old..+31).
__device__ __forceinline__ void strip_compute(
    uint32_t Ab, uint32_t Bb, int n_base,
    int a_row_off, int a_c_off, int b_row_off, int b_c_off,
    float (&aN)[2][4][4], float (&aO)[2][4][4],
    int row_old, int lid)
{
    #pragma unroll
    for (int i = 0; i < 2; i++)
        #pragma unroll
        for (int j = 0; j < 4; j++)
            #pragma unroll
            for (int r = 0; r < 4; r++) aN[i][j][r] = 0.0f;

    float lo[2] = {0.f, 0.f}, hi[2] = {0.f, 0.f};

    #pragma unroll
    for (int kk = 0; kk < 16; kk++) {
        uint32_t a[2][4];
        #pragma unroll
        for (int mi = 0; mi < 2; mi++) {
            int row = mi * 16 + a_row_off;
            int c = kk * 2 + a_c_off;
            LDSM4(a[mi][0], a[mi][1], a[mi][2], a[mi][3], SWA(Ab, row, c));
        }
        uint32_t b[2][4];
        #pragma unroll
        for (int p = 0; p < 2; p++) {
            int nrow = n_base + p * 16 + b_row_off;
            int c = kk * 2 + b_c_off;
            LDSM4(b[p][0], b[p][1], b[p][2], b[p][3], SWA(Bb, nrow, c));
        }
        // Interleave 2 elements of the previous strip's exp-epilogue.
        #pragma unroll
        for (int j = 0; j < 2; j++) {
            int e = kk * 2 + j;                    // 0..31
            int mi = e >> 4, ni = (e >> 2) & 3, r = e & 3;
            float v = ex2f(aO[mi][ni][r]);
            if (r < 2) lo[mi] += v; else hi[mi] += v;
        }
        #pragma unroll
        for (int mi = 0; mi < 2; mi++)
            #pragma unroll
            for (int ni = 0; ni < 4; ni++)
                MMA16816(aN[mi][ni], a[mi],
                         b[ni >> 1][(ni & 1) << 1],
                         b[ni >> 1][((ni & 1) << 1) + 1]);
    }

    // Finish previous strip: quad-shuffle row reduce + atomics.
    const int g = lid >> 2;
    #pragma unroll
    for (int mi = 0; mi < 2; mi++) {
        float l = lo[mi], h = hi[mi];
        l += __shfl_xor_sync(0xFFFFFFFFu, l, 1);
        l += __shfl_xor_sync(0xFFFFFFFFu, l, 2);
        h += __shfl_xor_sync(0xFFFFFFFFu, h, 1);
        h += __shfl_xor_sync(0xFFFFFFFFu, h, 2);
        if ((lid & 3) == 0) {
            atomicAdd(&g_rowsum[row_old + mi * 16 + g], l);
            atomicAdd(&g_rowsum[row_old + mi * 16 + g + 8], h);
        }
    }
}

// Epilogue-only flush for the final strip.
__device__ __forceinline__ void flush_acc(float (&aO)[2][4][4], int row_old, int lid) {
    const int g = lid >> 2;
    #pragma unroll
    for (int mi = 0; mi < 2; mi++) {
        float l = 0.f, h = 0.f;
        #pragma unroll
        for (int ni = 0; ni < 4; ni++) {
            l += ex2f(aO[mi][ni][0]) + ex2f(aO[mi][ni][1]);
            h += ex2f(aO[mi][ni][2]) + ex2f(aO[mi][ni][3]);
        }
        l += __shfl_xor_sync(0xFFFFFFFFu, l, 1);
        l += __shfl_xor_sync(0xFFFFFFFFu, l, 2);
        h += __shfl_xor_sync(0xFFFFFFFFu, h, 1);
        h += __shfl_xor_sync(0xFFFFFFFFu, h, 2);
        if ((lid & 3) == 0) {
            atomicAdd(&g_rowsum[row_old + mi * 16 + g], l);
            atomicAdd(&g_rowsum[row_old + mi * 16 + g + 8], h);
        }
    }
}

__global__ __launch_bounds__(THREADS, 2) void simsum_hmma_kernel() {
    extern __shared__ char smem[];
    const uint32_t sb = smem_to_u32(smem);
    const int tid = threadIdx.x;
    const int wid = tid >> 5, lid = tid & 31;
    const int n_base = wid * 32;               // warp grid 1 (M) x 4 (N)

    const int sub = lid >> 3, l7 = lid & 7;
    const int a_row_off = ((sub & 1) << 3) + l7;
    const int a_c_off   = sub >> 1;
    const int b_row_off = ((sub >> 1) << 3) + l7;
    const int b_c_off   = sub & 1;

    const int start = (int)(((long)blockIdx.x * TSTRIPS) / GRIDSZ);
    const int end   = (int)(((long)(blockIdx.x + 1) * TSTRIPS) / GRIDSZ);

    // Ping-pong accumulators; init so the first (fake) epilogue adds 0.
    float accA[2][4][4], accB[2][4][4];
    #pragma unroll
    for (int i = 0; i < 2; i++)
        #pragma unroll
        for (int j = 0; j < 4; j++)
            #pragma unroll
            for (int r = 0; r < 4; r++) { accA[i][j][r] = -1e30f; accB[i][j][r] = -1e30f; }

    int row_old = 0;
    int pcur = 0;
    for (int w = start; w < end; w++) {
        const int band = w >> 8, srow = w & (SPB - 1);
        if (srow == 0 || w == start) {
            CP_WAIT0();
            __syncthreads();                   // all warps done with old B panel
            load_B_panel(sb + SM_B, band, tid);
            load_A_strip(sb + SM_A(0), srow, tid);
            CP_COMMIT();
            CP_WAIT0();
            __syncthreads();
            pcur = 0;
        } else {
            CP_WAIT0();                        // prefetched A strip landed
            __syncthreads();
        }
        const bool pf = (w + 1 < end) && (((w + 1) & (SPB - 1)) != 0);
        if (pf) {
            load_A_strip(sb + SM_A(pcur ^ 1), srow + 1, tid);
            CP_COMMIT();
        }

        if ((w - start) & 1)
            strip_compute(sb + SM_A(pcur), sb + SM_B, n_base,
                          a_row_off, a_c_off, b_row_off, b_c_off,
                          accB, accA, row_old, lid);
        else
            strip_compute(sb + SM_A(pcur), sb + SM_B, n_base,
                          a_row_off, a_c_off, b_row_off, b_c_off,
                          accA, accB, row_old, lid);

        row_old = srow * SROWS;
        if (pf) pcur ^= 1;
    }

    if ((end - start) & 1) flush_acc(accA, row_old, lid);
    else                   flush_acc(accB, row_old, lid);
}

// ---------------------------------------------------------------------------
// Kernel: final loss — one row per thread, 32 blocks, atomic accumulate.
// ---------------------------------------------------------------------------
__global__ __launch_bounds__(256) void loss_kernel(float* __restrict__ out) {
    __shared__ float sh[256];
    int i = blockIdx.x * 256 + threadIdx.x;
    float d = g_diag[i] * INV_TEMP;
    float lneg = g_rowsum[i] - __expf(d);
    sh[threadIdx.x] = logf(lneg) - d;
    __syncthreads();
    #pragma unroll
    for (int o = 128; o > 0; o >>= 1) {
        if (threadIdx.x < o) sh[threadIdx.x] += sh[threadIdx.x + o];
        __syncthreads();
    }
    if (threadIdx.x == 0) atomicAdd(out, sh[0] * (1.0f / NROWS));
}

// ---------------------------------------------------------------------------
// Entry point
// ---------------------------------------------------------------------------
extern "C" void kernel_launch(void* const* d_in, const int* in_sizes, int n_in,
                              void* d_out, int out_size) {
    const float* X = (const float*)d_in[0];
    const float* Y = (const float*)d_in[1];
    float* out = (float*)d_out;

    static bool attr_set = false;
    if (!attr_set) {
        cudaFuncSetAttribute(simsum_hmma_kernel,
                             cudaFuncAttributeMaxDynamicSharedMemorySize, SMEM_TOTAL);
        attr_set = true;
    }

    prep_kernel<<<NROWS / 8, 256>>>(X, Y, out);
    simsum_hmma_kernel<<<GRIDSZ, THREADS, SMEM_TOTAL>>>();
    loss_kernel<<<NROWS / 256, 256>>>(out);
}